// round 1
// baseline (speedup 1.0000x reference)
#include <cuda_runtime.h>
#include <cstdint>

// Problem constants (fixed shapes per reference: B=256, L=512, N=50000)
constexpr int B_SZ   = 256;
constexpr int L_SEQ  = 512;
constexpr int N_LOC  = 50000;
constexpr int HSIZE  = 1024;          // hash slots (power of 2), load factor <= 0.5
constexpr int SEGS   = 8;             // column segments per row
constexpr int SEG_LEN = 6256;         // multiple of 16; 8*6256 = 50048 >= 50000
constexpr int NTHREADS = 256;

__global__ __launch_bounds__(NTHREADS, 4)
void loc_hist_kernel(const int* __restrict__ loc_seq,
                     const int* __restrict__ mask,
                     const float* __restrict__ rw_p,
                     const float* __restrict__ fw_p,
                     float* __restrict__ out)
{
    const int b   = blockIdx.x / SEGS;
    const int seg = blockIdx.x % SEGS;
    const int tid = threadIdx.x;

    __shared__ int      h_key[HSIZE];
    __shared__ int      h_cnt[HSIZE];
    __shared__ unsigned h_rec[HSIZE];   // float bits; all values >= 0 so uint max == float max
    __shared__ int      s_maxcnt;

    // ---- init hash ----
    #pragma unroll 4
    for (int i = tid; i < HSIZE; i += NTHREADS) {
        h_key[i] = -1;
        h_cnt[i] = 0;
        h_rec[i] = 0u;
    }
    if (tid == 0) s_maxcnt = 0;
    __syncthreads();

    const float rw   = *rw_p;
    const float l2rw = log2f(rw);

    // ---- insert the 512 timesteps (2 per thread) ----
    const int* lrow = loc_seq + (size_t)b * L_SEQ;
    const int* mrow = mask    + (size_t)b * L_SEQ;
    #pragma unroll
    for (int t = tid; t < L_SEQ; t += NTHREADS) {
        const int key = lrow[t];
        const int m   = mrow[t];
        // rec_val = rw^(L-1-t) if valid else 0
        const float rec = m ? exp2f((float)(L_SEQ - 1 - t) * l2rw) : 0.0f;

        unsigned h = ((unsigned)key * 2654435761u) & (HSIZE - 1);
        for (;;) {
            int cur = h_key[h];
            if (cur == key) break;
            if (cur == -1) {
                int prev = atomicCAS(&h_key[h], -1, key);
                if (prev == -1 || prev == key) break;
            }
            h = (h + 1) & (HSIZE - 1);
        }
        atomicAdd(&h_cnt[h], m);
        atomicMax(&h_rec[h], __float_as_uint(rec));
    }
    __syncthreads();

    // ---- block reduce: max frequency count over the row ----
    int mf = 0;
    #pragma unroll 4
    for (int i = tid; i < HSIZE; i += NTHREADS) mf = max(mf, h_cnt[i]);
    #pragma unroll
    for (int o = 16; o > 0; o >>= 1) mf = max(mf, __shfl_xor_sync(0xFFFFFFFFu, mf, o));
    if ((tid & 31) == 0) atomicMax(&s_maxcnt, mf);
    __syncthreads();

    const float fw  = *fw_p;
    const float inv = fw / fmaxf((float)s_maxcnt, 1.0f);

    // ---- zero-fill my column segment (float4 stores) ----
    const int col0 = seg * SEG_LEN;
    const int col1 = min(col0 + SEG_LEN, N_LOC);
    float* row = out + (size_t)b * N_LOC;
    float4* row4 = reinterpret_cast<float4*>(row);
    const float4 z = make_float4(0.f, 0.f, 0.f, 0.f);
    for (int i = col0 / 4 + tid; i < col1 / 4; i += NTHREADS)
        row4[i] = z;
    __syncthreads();

    // ---- scatter hash entries falling in my segment ----
    #pragma unroll 4
    for (int i = tid; i < HSIZE; i += NTHREADS) {
        const int key = h_key[i];
        if (key >= col0 && key < col1) {
            row[key] = __uint_as_float(h_rec[i]) + (float)h_cnt[i] * inv;
        }
    }
}

extern "C" void kernel_launch(void* const* d_in, const int* in_sizes, int n_in,
                              void* d_out, int out_size)
{
    const int*   loc_seq = (const int*)  d_in[0];   // (B, L) int32
    const int*   mask    = (const int*)  d_in[1];   // (B, L) int32
    const float* rw      = (const float*)d_in[2];   // scalar
    const float* fw      = (const float*)d_in[3];   // scalar
    float*       out     = (float*)d_out;           // (B, N) float32

    loc_hist_kernel<<<B_SZ * SEGS, NTHREADS>>>(loc_seq, mask, rw, fw, out);
}

// round 2
// speedup vs baseline: 1.2120x; 1.2120x over previous
#include <cuda_runtime.h>
#include <cstdint>

// Problem constants (fixed shapes per reference: B=256, L=512, N=50000)
constexpr int B_SZ    = 256;
constexpr int L_SEQ   = 512;
constexpr int N_LOC   = 50000;
constexpr int HSIZE   = 1024;          // hash slots (power of 2), load factor <= 0.5
constexpr int SEGS    = 8;             // column segments per row
constexpr int SEG_LEN = 6256;          // multiple of 4; 8*6256 = 50048 >= 50000
constexpr int CAP     = 512;           // max distinct keys per (row,seg) = L_SEQ worst case
constexpr int NT      = 256;

// Global scratch (allowed: __device__ arrays, no runtime alloc)
__device__ int   g_cnt[B_SZ * SEGS];
__device__ int   g_key[B_SZ * SEGS * CAP];
__device__ float g_val[B_SZ * SEGS * CAP];

// ---------------------------------------------------------------------------
// Kernel 1: one block per batch row. Build dedup hash in smem, reduce max
// frequency, emit final value per distinct key compacted into per-segment
// buckets in global scratch.
// ---------------------------------------------------------------------------
__global__ __launch_bounds__(NT, 4)
void build_kernel(const int* __restrict__ loc_seq,
                  const int* __restrict__ mask,
                  const float* __restrict__ rw_p,
                  const float* __restrict__ fw_p)
{
    const int b   = blockIdx.x;
    const int tid = threadIdx.x;

    __shared__ int      h_key[HSIZE];
    __shared__ int      h_cnt[HSIZE];
    __shared__ unsigned h_rec[HSIZE];   // float bits; all values >= 0
    __shared__ int      s_maxcnt;
    __shared__ int      s_segc[SEGS];

    #pragma unroll 4
    for (int i = tid; i < HSIZE; i += NT) {
        h_key[i] = -1;
        h_cnt[i] = 0;
        h_rec[i] = 0u;
    }
    if (tid == 0) s_maxcnt = 0;
    if (tid < SEGS) s_segc[tid] = 0;
    __syncthreads();

    const float l2rw = log2f(*rw_p);

    // vectorized load of 2 timesteps per thread
    const int2* lrow = reinterpret_cast<const int2*>(loc_seq + (size_t)b * L_SEQ);
    const int2* mrow = reinterpret_cast<const int2*>(mask    + (size_t)b * L_SEQ);
    const int2 lk = lrow[tid];
    const int2 mk = mrow[tid];

    #pragma unroll
    for (int j = 0; j < 2; j++) {
        const int t   = 2 * tid + j;
        const int key = (j == 0) ? lk.x : lk.y;
        const int m   = (j == 0) ? mk.x : mk.y;
        const float rec = m ? exp2f((float)(L_SEQ - 1 - t) * l2rw) : 0.0f;

        unsigned h = ((unsigned)key * 2654435761u) & (HSIZE - 1);
        for (;;) {
            int cur = h_key[h];
            if (cur == key) break;
            if (cur == -1) {
                int prev = atomicCAS(&h_key[h], -1, key);
                if (prev == -1 || prev == key) break;
            }
            h = (h + 1) & (HSIZE - 1);
        }
        atomicAdd(&h_cnt[h], m);
        atomicMax(&h_rec[h], __float_as_uint(rec));
    }
    __syncthreads();

    // block reduce: max frequency count
    int mf = 0;
    #pragma unroll 4
    for (int i = tid; i < HSIZE; i += NT) mf = max(mf, h_cnt[i]);
    #pragma unroll
    for (int o = 16; o > 0; o >>= 1) mf = max(mf, __shfl_xor_sync(0xFFFFFFFFu, mf, o));
    if ((tid & 31) == 0) atomicMax(&s_maxcnt, mf);
    __syncthreads();

    const float inv = (*fw_p) / fmaxf((float)s_maxcnt, 1.0f);

    // compact: final value per distinct key, bucketed by output segment
    #pragma unroll 4
    for (int i = tid; i < HSIZE; i += NT) {
        const int key = h_key[i];
        if (key >= 0) {
            const float val = __uint_as_float(h_rec[i]) + (float)h_cnt[i] * inv;
            const int seg = key / SEG_LEN;
            const int pos = atomicAdd(&s_segc[seg], 1);
            const int base = (b * SEGS + seg) * CAP;
            g_key[base + pos] = key;
            g_val[base + pos] = val;
        }
    }
    __syncthreads();
    if (tid < SEGS) g_cnt[b * SEGS + tid] = s_segc[tid];
}

// ---------------------------------------------------------------------------
// Kernel 2: one block per (row, segment). Zero-fill the segment with float4
// stores, then scatter the precomputed entries for this segment.
// ---------------------------------------------------------------------------
__global__ __launch_bounds__(NT, 8)
void fill_kernel(float* __restrict__ out)
{
    const int b   = blockIdx.x / SEGS;
    const int seg = blockIdx.x % SEGS;
    const int tid = threadIdx.x;

    const int col0 = seg * SEG_LEN;
    const int col1 = min(col0 + SEG_LEN, N_LOC);

    float*  row  = out + (size_t)b * N_LOC;
    float4* row4 = reinterpret_cast<float4*>(row);
    const float4 z = make_float4(0.f, 0.f, 0.f, 0.f);

    #pragma unroll 2
    for (int i = col0 / 4 + tid; i < col1 / 4; i += NT)
        row4[i] = z;

    const int slot = b * SEGS + seg;
    const int n    = g_cnt[slot];
    const int base = slot * CAP;

    __syncthreads();

    for (int i = tid; i < n; i += NT)
        row[g_key[base + i]] = g_val[base + i];
}

extern "C" void kernel_launch(void* const* d_in, const int* in_sizes, int n_in,
                              void* d_out, int out_size)
{
    const int*   loc_seq = (const int*)  d_in[0];   // (B, L) int32
    const int*   mask    = (const int*)  d_in[1];   // (B, L) int32
    const float* rw      = (const float*)d_in[2];   // scalar
    const float* fw      = (const float*)d_in[3];   // scalar
    float*       out     = (float*)d_out;           // (B, N) float32

    build_kernel<<<B_SZ, NT>>>(loc_seq, mask, rw, fw);
    fill_kernel<<<B_SZ * SEGS, NT>>>(out);
}